// round 11
// baseline (speedup 1.0000x reference)
#include <cuda_runtime.h>
#include <cuda_bf16.h>

#define NT 48
#define SEQ 512
#define BATCH 1024
#define BPB 4                 // batches per block (2 per thread)
#define THREADS 96            // (BPB/2) * NT = 3 warps

// Fused (value, float-index) argmax tree over 48 entries.
// Strict r>l per node, left carries the lower index => exact
// first-occurrence argmax (jnp semantics); values bit-exact (FMNMX only).
__device__ __forceinline__ void argmax48(const float4* __restrict__ sp,
                                         const float* __restrict__ tc,
                                         float& m_out, float& fidx_out)
{
    float s[NT];
#pragma unroll
    for (int k = 0; k < NT / 4; k++) {
        float4 q = sp[k];
        s[4 * k + 0] = q.x + tc[4 * k + 0];
        s[4 * k + 1] = q.y + tc[4 * k + 1];
        s[4 * k + 2] = q.z + tc[4 * k + 2];
        s[4 * k + 3] = q.w + tc[4 * k + 3];
    }
    float v1[24], i1[24];
#pragma unroll
    for (int k = 0; k < 24; k++) {
        const bool pr = (s[2 * k + 1] > s[2 * k]);
        v1[k] = fmaxf(s[2 * k], s[2 * k + 1]);
        i1[k] = pr ? (float)(2 * k + 1) : (float)(2 * k);
    }
    float v2[12], i2[12];
#pragma unroll
    for (int k = 0; k < 12; k++) {
        const bool pr = (v1[2 * k + 1] > v1[2 * k]);
        v2[k] = fmaxf(v1[2 * k], v1[2 * k + 1]);
        i2[k] = pr ? i1[2 * k + 1] : i1[2 * k];
    }
    float v3[6], i3[6];
#pragma unroll
    for (int k = 0; k < 6; k++) {
        const bool pr = (v2[2 * k + 1] > v2[2 * k]);
        v3[k] = fmaxf(v2[2 * k], v2[2 * k + 1]);
        i3[k] = pr ? i2[2 * k + 1] : i2[2 * k];
    }
    float v4[3], i4[3];
#pragma unroll
    for (int k = 0; k < 3; k++) {
        const bool pr = (v3[2 * k + 1] > v3[2 * k]);
        v4[k] = fmaxf(v3[2 * k], v3[2 * k + 1]);
        i4[k] = pr ? i3[2 * k + 1] : i3[2 * k];
    }
    const bool p01 = (v4[1] > v4[0]);
    const float mv01 = fmaxf(v4[0], v4[1]);
    const float mi01 = p01 ? i4[1] : i4[0];
    const bool p2  = (v4[2] > mv01);
    m_out    = fmaxf(mv01, v4[2]);
    fidx_out = p2 ? i4[2] : mi01;
}

// Viterbi forward, dual-stream threads: thread (lb, j) processes tag j for
// TWO batches (2*lb, 2*lb+1 within the block). tc[48] shared across streams;
// two independent LDS->tree chains per step fill latency bubbles (ILP).
// One barrier per step serves both streams. Bit-exact vs reference.
__global__ __launch_bounds__(THREADS, 2)
void crf_viterbi_kernel(const float* __restrict__ pot,
                        const float* __restrict__ trans,
                        float* __restrict__ out)
{
    __shared__ __align__(16) float st[2][BPB][NT];

    const int tid = threadIdx.x;
    const int lb  = tid / NT;            // 0/1 -> batch pair within block
    const int j   = tid - lb * NT;
    const int b0  = blockIdx.x * BPB + 2 * lb;   // first batch of this thread
    const int b1  = b0 + 1;

    // Transition column T[i][j] — shared by both streams
    float tc[NT];
#pragma unroll
    for (int i = 0; i < NT; i++) tc[i] = trans[i * NT + j];

    const float* potA = pot + (size_t)b0 * SEQ * NT + j;
    const float* potB = pot + (size_t)b1 * SEQ * NT + j;
    float* bppA       = out + (size_t)b0 * (SEQ - 1) * NT + j;
    float* bppB       = out + (size_t)b1 * (SEQ - 1) * NT + j;
    float* scores     = out + (size_t)BATCH * (SEQ - 1) * NT;

    float nsA = potA[0];
    float nsB = potB[0];
    st[0][2 * lb + 0][j] = nsA;
    st[0][2 * lb + 1][j] = nsB;
    __syncthreads();

    // 2-deep prefetch per stream, running pointers
    const float* ppA = potA + 3 * NT;
    const float* ppB = potB + 3 * NT;
    float pA1 = potA[NT],     pB1 = potB[NT];
    float pA2 = potA[2 * NT], pB2 = potB[2 * NT];
    int buf = 0;

#pragma unroll 2
    for (int t = 1; t < SEQ; ++t) {
        const float pA = pA1, pB = pB1;
        pA1 = pA2; pB1 = pB2;
        if (t + 2 < SEQ) {
            pA2 = *ppA; ppA += NT;
            pB2 = *ppB; ppB += NT;
        }

        float mA, fiA, mB, fiB;
        argmax48((const float4*)st[buf][2 * lb + 0], tc, mA, fiA);
        argmax48((const float4*)st[buf][2 * lb + 1], tc, mB, fiB);

        nsA = pA + mA;                    // bit-exact vs reference
        nsB = pB + mB;
        st[buf ^ 1][2 * lb + 0][j] = nsA;
        st[buf ^ 1][2 * lb + 1][j] = nsB;
        bppA[0] = fiA; bppA += NT;
        bppB[0] = fiB; bppB += NT;
        __syncthreads();
        buf ^= 1;
    }

    scores[(size_t)b0 * NT + j] = nsA;
    scores[(size_t)b1 * NT + j] = nsB;
}

extern "C" void kernel_launch(void* const* d_in, const int* in_sizes, int n_in,
                              void* d_out, int out_size)
{
    const float* pot   = (const float*)d_in[0];
    const float* trans = (const float*)d_in[1];
    float* out         = (float*)d_out;
    crf_viterbi_kernel<<<BATCH / BPB, THREADS>>>(pot, trans, out);
}

// round 12
// speedup vs baseline: 1.5892x; 1.5892x over previous
#include <cuda_runtime.h>
#include <cuda_bf16.h>

#define NT 48
#define SEQ 512
#define BATCH 1024

// ---------------- fused (value, float-index) argmax trees -----------------
// Strict r>l per node, left operand always carries the lower index =>
// exact first-occurrence argmax (jnp semantics); values bit-exact (FMNMX).

__device__ __forceinline__ void argmax48(const float4* __restrict__ sp,
                                         const float* __restrict__ tc,
                                         float& m_out, float& fidx_out)
{
    float s[48];
#pragma unroll
    for (int k = 0; k < 12; k++) {
        float4 q = sp[k];
        s[4 * k + 0] = q.x + tc[4 * k + 0];
        s[4 * k + 1] = q.y + tc[4 * k + 1];
        s[4 * k + 2] = q.z + tc[4 * k + 2];
        s[4 * k + 3] = q.w + tc[4 * k + 3];
    }
    float v1[24], i1[24];
#pragma unroll
    for (int k = 0; k < 24; k++) {
        const bool pr = (s[2 * k + 1] > s[2 * k]);
        v1[k] = fmaxf(s[2 * k], s[2 * k + 1]);
        i1[k] = pr ? (float)(2 * k + 1) : (float)(2 * k);
    }
    float v2[12], i2[12];
#pragma unroll
    for (int k = 0; k < 12; k++) {
        const bool pr = (v1[2 * k + 1] > v1[2 * k]);
        v2[k] = fmaxf(v1[2 * k], v1[2 * k + 1]);
        i2[k] = pr ? i1[2 * k + 1] : i1[2 * k];
    }
    float v3[6], i3[6];
#pragma unroll
    for (int k = 0; k < 6; k++) {
        const bool pr = (v2[2 * k + 1] > v2[2 * k]);
        v3[k] = fmaxf(v2[2 * k], v2[2 * k + 1]);
        i3[k] = pr ? i2[2 * k + 1] : i2[2 * k];
    }
    float v4[3], i4[3];
#pragma unroll
    for (int k = 0; k < 3; k++) {
        const bool pr = (v3[2 * k + 1] > v3[2 * k]);
        v4[k] = fmaxf(v3[2 * k], v3[2 * k + 1]);
        i4[k] = pr ? i3[2 * k + 1] : i3[2 * k];
    }
    const bool p01 = (v4[1] > v4[0]);
    const float mv01 = fmaxf(v4[0], v4[1]);
    const float mi01 = p01 ? i4[1] : i4[0];
    const bool p2 = (v4[2] > mv01);
    m_out    = fmaxf(mv01, v4[2]);
    fidx_out = p2 ? i4[2] : mi01;
}

// 24-entry variant; returns LOCAL index 0..23.
__device__ __forceinline__ void argmax24(const float4* __restrict__ sp,
                                         const float* __restrict__ tc,
                                         float& m_out, float& fidx_out)
{
    float s[24];
#pragma unroll
    for (int k = 0; k < 6; k++) {
        float4 q = sp[k];
        s[4 * k + 0] = q.x + tc[4 * k + 0];
        s[4 * k + 1] = q.y + tc[4 * k + 1];
        s[4 * k + 2] = q.z + tc[4 * k + 2];
        s[4 * k + 3] = q.w + tc[4 * k + 3];
    }
    float v1[12], i1[12];
#pragma unroll
    for (int k = 0; k < 12; k++) {
        const bool pr = (s[2 * k + 1] > s[2 * k]);
        v1[k] = fmaxf(s[2 * k], s[2 * k + 1]);
        i1[k] = pr ? (float)(2 * k + 1) : (float)(2 * k);
    }
    float v2[6], i2[6];
#pragma unroll
    for (int k = 0; k < 6; k++) {
        const bool pr = (v1[2 * k + 1] > v1[2 * k]);
        v2[k] = fmaxf(v1[2 * k], v1[2 * k + 1]);
        i2[k] = pr ? i1[2 * k + 1] : i1[2 * k];
    }
    float v3[3], i3[3];
#pragma unroll
    for (int k = 0; k < 3; k++) {
        const bool pr = (v2[2 * k + 1] > v2[2 * k]);
        v3[k] = fmaxf(v2[2 * k], v2[2 * k + 1]);
        i3[k] = pr ? i2[2 * k + 1] : i2[2 * k];
    }
    const bool p01 = (v3[1] > v3[0]);
    const float mv01 = fmaxf(v3[0], v3[1]);
    const float mi01 = p01 ? i3[1] : i3[0];
    const bool p2 = (v3[2] > mv01);
    m_out    = fmaxf(mv01, v3[2]);
    fidx_out = p2 ? i3[2] : mi01;
}

// Warp-autonomous Viterbi: one warp (one block) per batch, grid = 1024.
//   lane l: owns tag j1 = l (argmax48) AND half of tag j2 = 32 + (l>>1)
//   (argmax24 over i in [24h, 24h+24), h = l&1, merged with partner l^1
//   via shfl_xor). State in SMEM (48 floats, double buffered), __syncwarp
//   only — no cross-warp barrier, minimal wave-quantization (1024 blocks).
__global__ __launch_bounds__(32, 8)
void crf_viterbi_kernel(const float* __restrict__ pot,
                        const float* __restrict__ trans,
                        float* __restrict__ out)
{
    __shared__ __align__(16) float st[2][NT];

    const int l  = threadIdx.x;
    const int b  = blockIdx.x;
    const int j1 = l;
    const int h  = l & 1;
    const int j2 = 32 + (l >> 1);
    const int ib2 = h * 24;                 // i-base of this lane's half
    const float ib2f = (float)ib2;

    // tc1: full column for j1; tc2: this lane's half-column for j2
    float tc1[NT];
#pragma unroll
    for (int i = 0; i < NT; i++) tc1[i] = trans[i * NT + j1];
    float tc2[24];
#pragma unroll
    for (int k = 0; k < 24; k++) tc2[k] = trans[(ib2 + k) * NT + j2];

    const float* potb = pot + (size_t)b * SEQ * NT;
    float* bpb        = out + (size_t)b * (SEQ - 1) * NT;
    float* scores     = out + (size_t)BATCH * (SEQ - 1) * NT + (size_t)b * NT;

    // init_state = potentials[:, 0]
    float ns1 = potb[j1];
    float ns2 = potb[j2];
    st[0][j1] = ns1;
    if (h == 0) st[0][j2] = ns2;
    __syncwarp();

    // 2-deep prefetch per stream, running pointers
    const float* pp1 = potb + 3 * NT + j1;
    const float* pp2 = potb + 3 * NT + j2;
    float p1a = potb[NT + j1],     p2a = potb[NT + j2];
    float p1b = potb[2 * NT + j1], p2b = potb[2 * NT + j2];
    int buf = 0;

#pragma unroll 2
    for (int t = 1; t < SEQ; ++t) {
        const float p1 = p1a, p2 = p2a;
        p1a = p1b; p2a = p2b;
        if (t + 2 < SEQ) {
            p1b = *pp1; pp1 += NT;
            p2b = *pp2; pp2 += NT;
        }

        float m1, fi1, m2, fi2l;
        argmax48((const float4*)st[buf], tc1, m1, fi1);
        argmax24((const float4*)(st[buf] + ib2), tc2, m2, fi2l);
        float fi2 = fi2l + ib2f;

        // Partner merge for j2 (adjacent lane). Tie -> lower index: exact.
        const float mo = __shfl_xor_sync(0xffffffffu, m2, 1);
        const float io = __shfl_xor_sync(0xffffffffu, fi2, 1);
        if (mo > m2 || (mo == m2 && io < fi2)) { m2 = mo; fi2 = io; }

        ns1 = p1 + m1;                      // bit-exact vs reference
        ns2 = p2 + m2;
        st[buf ^ 1][j1] = ns1;
        if (h == 0) st[buf ^ 1][j2] = ns2;
        bpb[j1] = fi1;                      // coalesced 128B
        if (h == 1) bpb[j2] = fi2;          // 64B
        bpb += NT;
        __syncwarp();
        buf ^= 1;
    }

    scores[j1] = ns1;
    if (h == 0) scores[j2] = ns2;
}

extern "C" void kernel_launch(void* const* d_in, const int* in_sizes, int n_in,
                              void* d_out, int out_size)
{
    const float* pot   = (const float*)d_in[0];
    const float* trans = (const float*)d_in[1];
    float* out         = (float*)d_out;
    crf_viterbi_kernel<<<BATCH, 32>>>(pot, trans, out);
}